// round 5
// baseline (speedup 1.0000x reference)
#include <cuda_runtime.h>
#include <cuda_fp16.h>
#include <cstdint>

// ============================================================
// Problem dims (fixed per reference)
// ============================================================
#define M_TOTAL 16384   // B*S
#define N_TOTAL 4096    // D_OUT
#define K_TOTAL 4096    // D_IN

// CTA tile
#define BM 128
#define BN 256
#define BK 64
#define STAGES 3
#define KITERS (K_TOTAL / BK)     // 64
#define GRID_N (N_TOTAL / BN)     // 16
#define GRID_M (M_TOTAL / BM)     // 128

#define NTHREADS 256              // 8 warps: 2 (M) x 4 (N), warp tile 64x64

// Smem: padded rows -> conflict-free ldmatrix phases.
// 64 halves data + 8 halves pad = 72 halves = 144B row stride.
#define PAD_LD 72
#define ROW_BYTES (PAD_LD * 2)                   // 144
#define A_STAGE_BYTES (BM * ROW_BYTES)           // 18432
#define B_STAGE_BYTES (BN * ROW_BYTES)           // 36864
#define STAGE_BYTES   (A_STAGE_BYTES + B_STAGE_BYTES)   // 55296
#define SMEM_BIAS_BYTES 1024
#define SMEM_TOTAL (SMEM_BIAS_BYTES + STAGES * STAGE_BYTES)  // 166912
#define EPI_PITCH 260   // floats; 1040B rows -> 16B aligned

// fp16 scratch (static device globals: no runtime allocation)
__device__ __align__(1024) __half g_xh[(size_t)M_TOTAL * K_TOTAL];
__device__ __align__(1024) __half g_wh[(size_t)N_TOTAL * K_TOTAL];

// ============================================================
// PTX helpers (sm_80 base ISA — safe under compute_103)
// ============================================================
__device__ __forceinline__ uint32_t smem_to_u32(const void* p) {
    uint32_t a;
    asm("{ .reg .u64 t; cvta.to.shared.u64 t, %1; cvt.u32.u64 %0, t; }" : "=r"(a) : "l"(p));
    return a;
}

__device__ __forceinline__ void cp_async16(uint32_t saddr, const void* gptr) {
    asm volatile("cp.async.cg.shared.global [%0], [%1], 16;" :: "r"(saddr), "l"(gptr));
}

__device__ __forceinline__ void cp_commit() {
    asm volatile("cp.async.commit_group;");
}

template <int N>
__device__ __forceinline__ void cp_wait_group() {
    asm volatile("cp.async.wait_group %0;" :: "n"(N));
}

__device__ __forceinline__ void ldsm_x4(uint32_t& r0, uint32_t& r1, uint32_t& r2, uint32_t& r3,
                                        uint32_t addr) {
    asm volatile("ldmatrix.sync.aligned.m8n8.x4.shared.b16 {%0,%1,%2,%3}, [%4];"
        : "=r"(r0), "=r"(r1), "=r"(r2), "=r"(r3) : "r"(addr));
}

__device__ __forceinline__ void mma_16816(float& c0, float& c1, float& c2, float& c3,
                                          uint32_t a0, uint32_t a1, uint32_t a2, uint32_t a3,
                                          uint32_t b0, uint32_t b1) {
    asm volatile(
        "mma.sync.aligned.m16n8k16.row.col.f32.f16.f16.f32 "
        "{%0,%1,%2,%3}, {%4,%5,%6,%7}, {%8,%9}, {%0,%1,%2,%3};"
        : "+f"(c0), "+f"(c1), "+f"(c2), "+f"(c3)
        : "r"(a0), "r"(a1), "r"(a2), "r"(a3), "r"(b0), "r"(b1));
}

// ============================================================
// fp32 -> fp16 conversion (measured at ~74% DRAM roofline)
// ============================================================
__global__ void f32_to_f16_kernel(const float4* __restrict__ src, uint2* __restrict__ dst, int n4) {
    int i = blockIdx.x * blockDim.x + threadIdx.x;
    if (i < n4) {
        float4 v = src[i];
        __half2 a = __floats2half2_rn(v.x, v.y);
        __half2 b = __floats2half2_rn(v.z, v.w);
        uint2 o;
        o.x = *reinterpret_cast<uint32_t*>(&a);
        o.y = *reinterpret_cast<uint32_t*>(&b);
        dst[i] = o;
    }
}

// ============================================================
// GEMM: out[M,N] = x[M,K] @ W[N,K]^T + bias
// 3-stage cp.async pipeline, explicit ldmatrix + mma.sync.m16n8k16,
// single __syncthreads per K-iteration.
// ============================================================
__global__ void __launch_bounds__(NTHREADS, 1) gemm_f16_kernel(
    const __half* __restrict__ xh,
    const __half* __restrict__ wh,
    const float* __restrict__ bias,
    float* __restrict__ out)
{
    extern __shared__ char smem[];
    const uint32_t smem_u32 = smem_to_u32(smem);
    const int tid  = threadIdx.x;
    const int wid  = tid >> 5;
    const int lane = tid & 31;
    const int wm = wid >> 2;       // 0..1  (M warp)
    const int wn = wid & 3;        // 0..3  (N warp)

    const int tile_n = (int)(blockIdx.x % GRID_N);
    const int tile_m = (int)(blockIdx.x / GRID_N);
    const int m0 = tile_m * BM;
    const int n0 = tile_n * BN;

    // Stage bias tile into smem
    float* sbias = reinterpret_cast<float*>(smem);
    for (int i = tid; i < BN; i += NTHREADS) sbias[i] = bias[n0 + i];

    const __half* gA_base = xh + (size_t)m0 * K_TOTAL;
    const __half* gW_base = wh + (size_t)n0 * K_TOTAL;

    auto issue_copy = [&](int kt, int stage) {
        const uint32_t sa = smem_u32 + SMEM_BIAS_BYTES + (uint32_t)stage * STAGE_BYTES;
        const uint32_t sb = sa + A_STAGE_BYTES;
        const __half* gA = gA_base + kt * BK;
        const __half* gW = gW_base + kt * BK;
        // A: 128 rows x 8 chunks(16B) = 1024 chunks
        #pragma unroll
        for (int i = 0; i < 4; i++) {
            int idx = tid + i * NTHREADS;
            int r = idx >> 3, c = idx & 7;
            cp_async16(sa + (uint32_t)r * ROW_BYTES + (uint32_t)c * 16,
                       gA + (size_t)r * K_TOTAL + c * 8);
        }
        // B: 256 rows x 8 chunks = 2048 chunks
        #pragma unroll
        for (int i = 0; i < 8; i++) {
            int idx = tid + i * NTHREADS;
            int r = idx >> 3, c = idx & 7;
            cp_async16(sb + (uint32_t)r * ROW_BYTES + (uint32_t)c * 16,
                       gW + (size_t)r * K_TOTAL + c * 8);
        }
    };

    // Accumulators: 4 (m16) x 8 (n8) tiles, 4 floats each = 128 regs
    float acc[4][8][4];
    #pragma unroll
    for (int mi = 0; mi < 4; mi++)
        #pragma unroll
        for (int nj = 0; nj < 8; nj++)
            #pragma unroll
            for (int c = 0; c < 4; c++)
                acc[mi][nj][c] = 0.0f;

    // Pipeline prologue
    #pragma unroll
    for (int s = 0; s < STAGES - 1; s++) {
        issue_copy(s, s);
        cp_commit();
    }

    // ldmatrix lane addressing: rows = base + (lane&15), k-halfword-offset = (lane>>4)*8
    const uint32_t lane_row  = (uint32_t)(lane & 15) * ROW_BYTES;
    const uint32_t lane_koff = (uint32_t)(lane >> 4) * 16;   // bytes

    for (int kt = 0; kt < KITERS; kt++) {
        cp_wait_group<STAGES - 2>();
        __syncthreads();   // single sync per iter: also orders next issue vs prev compute

        int knext = kt + STAGES - 1;
        if (knext < KITERS) issue_copy(knext, knext % STAGES);
        cp_commit();

        const int stage = kt % STAGES;
        const uint32_t sa = smem_u32 + SMEM_BIAS_BYTES + (uint32_t)stage * STAGE_BYTES;
        const uint32_t sb = sa + A_STAGE_BYTES;
        const uint32_t a_base = sa + (uint32_t)(wm * 64) * ROW_BYTES + lane_row + lane_koff;
        const uint32_t b_base = sb + (uint32_t)(wn * 64) * ROW_BYTES + lane_row + lane_koff;

        #pragma unroll
        for (int ks = 0; ks < BK / 16; ks++) {
            const uint32_t koff = (uint32_t)ks * 32;   // 16 halves = 32 bytes
            uint32_t a[4][4], b[4][4];
            #pragma unroll
            for (int mi = 0; mi < 4; mi++)
                ldsm_x4(a[mi][0], a[mi][1], a[mi][2], a[mi][3],
                        a_base + (uint32_t)(mi * 16) * ROW_BYTES + koff);
            #pragma unroll
            for (int nb = 0; nb < 4; nb++)
                ldsm_x4(b[nb][0], b[nb][1], b[nb][2], b[nb][3],
                        b_base + (uint32_t)(nb * 16) * ROW_BYTES + koff);
            // a: {m0-7 k0-7, m8-15 k0-7, m0-7 k8-15, m8-15 k8-15} = mma A frag order
            // b: r0=n0-7 k0-7, r1=n8-15 k0-7, r2=n0-7 k8-15, r3=n8-15 k8-15
            #pragma unroll
            for (int mi = 0; mi < 4; mi++)
                #pragma unroll
                for (int nb = 0; nb < 4; nb++) {
                    mma_16816(acc[mi][nb*2][0], acc[mi][nb*2][1], acc[mi][nb*2][2], acc[mi][nb*2][3],
                              a[mi][0], a[mi][1], a[mi][2], a[mi][3], b[nb][0], b[nb][2]);
                    mma_16816(acc[mi][nb*2+1][0], acc[mi][nb*2+1][1], acc[mi][nb*2+1][2], acc[mi][nb*2+1][3],
                              a[mi][0], a[mi][1], a[mi][2], a[mi][3], b[nb][1], b[nb][3]);
                }
        }
    }
    __syncthreads();   // protect smem reuse for epilogue staging

    // ---- Epilogue: acc regs -> smem staging -> +bias -> coalesced gmem stores
    // m16n8 f32 frag layout: c0=[l/4][2*(l%4)], c1=[l/4][2*(l%4)+1], c2/c3 at row+8
    float* staging = reinterpret_cast<float*>(smem + SMEM_BIAS_BYTES);
    {
        const int r_in = lane >> 2;
        const int c_in = (lane & 3) * 2;
        #pragma unroll
        for (int mi = 0; mi < 4; mi++)
            #pragma unroll
            for (int nj = 0; nj < 8; nj++) {
                int rr = wm * 64 + mi * 16 + r_in;
                int cc = wn * 64 + nj * 8 + c_in;
                *reinterpret_cast<float2*>(staging + (size_t)rr * EPI_PITCH + cc)
                    = make_float2(acc[mi][nj][0], acc[mi][nj][1]);
                *reinterpret_cast<float2*>(staging + (size_t)(rr + 8) * EPI_PITCH + cc)
                    = make_float2(acc[mi][nj][2], acc[mi][nj][3]);
            }
    }
    __syncthreads();

    // Coalesced write-out: 128 rows x 64 float4
    #pragma unroll 4
    for (int idx = tid; idx < BM * (BN / 4); idx += NTHREADS) {
        int rr = idx >> 6;
        int c4 = idx & 63;
        float4 v = *reinterpret_cast<const float4*>(staging + (size_t)rr * EPI_PITCH + c4 * 4);
        v.x += sbias[c4 * 4 + 0];
        v.y += sbias[c4 * 4 + 1];
        v.z += sbias[c4 * 4 + 2];
        v.w += sbias[c4 * 4 + 3];
        *reinterpret_cast<float4*>(out + (size_t)(m0 + rr) * N_TOTAL + n0 + c4 * 4) = v;
    }
}

// ============================================================
// Host launcher
// ============================================================
extern "C" void kernel_launch(void* const* d_in, const int* in_sizes, int n_in,
                              void* d_out, int out_size) {
    const float* x    = (const float*)d_in[0];   // [16384, 4096]
    const float* w    = (const float*)d_in[1];   // [4096, 4096]
    const float* bias = (const float*)d_in[2];   // [4096]
    float* out = (float*)d_out;

    __half* xh = nullptr;
    __half* wh = nullptr;
    cudaGetSymbolAddress((void**)&xh, g_xh);
    cudaGetSymbolAddress((void**)&wh, g_wh);

    // fp32 -> fp16 conversion
    {
        int n4x = (int)(((size_t)M_TOTAL * K_TOTAL) / 4);
        int n4w = (int)(((size_t)N_TOTAL * K_TOTAL) / 4);
        f32_to_f16_kernel<<<(n4x + 255) / 256, 256>>>((const float4*)x, (uint2*)xh, n4x);
        f32_to_f16_kernel<<<(n4w + 255) / 256, 256>>>((const float4*)w, (uint2*)wh, n4w);
    }

    static bool attr_set = false;
    if (!attr_set) {
        cudaFuncSetAttribute(gemm_f16_kernel, cudaFuncAttributeMaxDynamicSharedMemorySize,
                             SMEM_TOTAL);
        attr_set = true;
    }
    gemm_f16_kernel<<<GRID_M * GRID_N, NTHREADS, SMEM_TOTAL>>>(xh, wh, bias, out);
}

// round 6
// speedup vs baseline: 1.0652x; 1.0652x over previous
#include <cuda_runtime.h>
#include <cuda_fp16.h>
#include <cstdint>

// ============================================================
// Problem dims (fixed per reference)
// ============================================================
#define M_TOTAL 16384   // B*S
#define N_TOTAL 4096    // D_OUT
#define K_TOTAL 4096    // D_IN

// CTA tile — sized for 2 CTAs/SM
#define BM 128
#define BN 128
#define BK 64
#define STAGES 3
#define KITERS (K_TOTAL / BK)     // 64
#define GRID_N (N_TOTAL / BN)     // 32
#define GRID_M (M_TOTAL / BM)     // 128
#define GROUP_M 16                // tile-order swizzle: M-tiles per N sweep

#define NTHREADS 256              // 8 warps: 2 (M) x 4 (N), warp tile 64x32

// Smem: padded rows -> conflict-free ldmatrix phases.
// 64 halves data + 8 halves pad = 72 halves = 144B row stride.
#define PAD_LD 72
#define ROW_BYTES (PAD_LD * 2)                   // 144
#define A_STAGE_BYTES (BM * ROW_BYTES)           // 18432
#define B_STAGE_BYTES (BN * ROW_BYTES)           // 18432
#define STAGE_BYTES   (A_STAGE_BYTES + B_STAGE_BYTES)   // 36864
#define SMEM_BIAS_BYTES 1024
#define SMEM_TOTAL (SMEM_BIAS_BYTES + STAGES * STAGE_BYTES)  // 111616 (x2 = 223232 <= 228KB)
#define EPI_PITCH 132   // floats; 528B rows -> 16B aligned

// fp16 scratch (static device globals: no runtime allocation)
__device__ __align__(1024) __half g_xh[(size_t)M_TOTAL * K_TOTAL];
__device__ __align__(1024) __half g_wh[(size_t)N_TOTAL * K_TOTAL];

// ============================================================
// PTX helpers (sm_80 base ISA — safe under compute_103)
// ============================================================
__device__ __forceinline__ uint32_t smem_to_u32(const void* p) {
    uint32_t a;
    asm("{ .reg .u64 t; cvta.to.shared.u64 t, %1; cvt.u32.u64 %0, t; }" : "=r"(a) : "l"(p));
    return a;
}

__device__ __forceinline__ void cp_async16(uint32_t saddr, const void* gptr) {
    asm volatile("cp.async.cg.shared.global [%0], [%1], 16;" :: "r"(saddr), "l"(gptr));
}

__device__ __forceinline__ void cp_commit() {
    asm volatile("cp.async.commit_group;");
}

template <int N>
__device__ __forceinline__ void cp_wait_group() {
    asm volatile("cp.async.wait_group %0;" :: "n"(N));
}

__device__ __forceinline__ void ldsm_x4(uint32_t& r0, uint32_t& r1, uint32_t& r2, uint32_t& r3,
                                        uint32_t addr) {
    asm volatile("ldmatrix.sync.aligned.m8n8.x4.shared.b16 {%0,%1,%2,%3}, [%4];"
        : "=r"(r0), "=r"(r1), "=r"(r2), "=r"(r3) : "r"(addr));
}

__device__ __forceinline__ void mma_16816(float& c0, float& c1, float& c2, float& c3,
                                          uint32_t a0, uint32_t a1, uint32_t a2, uint32_t a3,
                                          uint32_t b0, uint32_t b1) {
    asm volatile(
        "mma.sync.aligned.m16n8k16.row.col.f32.f16.f16.f32 "
        "{%0,%1,%2,%3}, {%4,%5,%6,%7}, {%8,%9}, {%0,%1,%2,%3};"
        : "+f"(c0), "+f"(c1), "+f"(c2), "+f"(c3)
        : "r"(a0), "r"(a1), "r"(a2), "r"(a3), "r"(b0), "r"(b1));
}

// ============================================================
// fp32 -> fp16 conversion (measured at ~74% DRAM roofline)
// ============================================================
__global__ void f32_to_f16_kernel(const float4* __restrict__ src, uint2* __restrict__ dst, int n4) {
    int i = blockIdx.x * blockDim.x + threadIdx.x;
    if (i < n4) {
        float4 v = src[i];
        __half2 a = __floats2half2_rn(v.x, v.y);
        __half2 b = __floats2half2_rn(v.z, v.w);
        uint2 o;
        o.x = *reinterpret_cast<uint32_t*>(&a);
        o.y = *reinterpret_cast<uint32_t*>(&b);
        dst[i] = o;
    }
}

// ============================================================
// GEMM: out[M,N] = x[M,K] @ W[N,K]^T + bias
// 3-stage cp.async pipeline, ldmatrix + mma.sync.m16n8k16,
// single __syncthreads per K-iteration, 2 CTAs/SM.
// ============================================================
__global__ void __launch_bounds__(NTHREADS, 2) gemm_f16_kernel(
    const __half* __restrict__ xh,
    const __half* __restrict__ wh,
    const float* __restrict__ bias,
    float* __restrict__ out)
{
    extern __shared__ char smem[];
    const uint32_t smem_u32 = smem_to_u32(smem);
    const int tid  = threadIdx.x;
    const int wid  = tid >> 5;
    const int lane = tid & 31;
    const int wm = wid >> 2;       // 0..1  (M warp) -> 64 rows each
    const int wn = wid & 3;        // 0..3  (N warp) -> 32 cols each

    // Swizzled tile order: GROUP_M M-tiles per N sweep (L2 reuse within a wave)
    const int group_size = GROUP_M * GRID_N;
    const int g  = (int)(blockIdx.x / group_size);
    const int r  = (int)(blockIdx.x % group_size);
    const int tile_m = g * GROUP_M + (r % GROUP_M);
    const int tile_n = r / GROUP_M;
    const int m0 = tile_m * BM;
    const int n0 = tile_n * BN;

    // Stage bias tile into smem
    float* sbias = reinterpret_cast<float*>(smem);
    for (int i = tid; i < BN; i += NTHREADS) sbias[i] = bias[n0 + i];

    const __half* gA_base = xh + (size_t)m0 * K_TOTAL;
    const __half* gW_base = wh + (size_t)n0 * K_TOTAL;

    auto issue_copy = [&](int kt, int stage) {
        const uint32_t sa = smem_u32 + SMEM_BIAS_BYTES + (uint32_t)stage * STAGE_BYTES;
        const uint32_t sb = sa + A_STAGE_BYTES;
        const __half* gA = gA_base + kt * BK;
        const __half* gW = gW_base + kt * BK;
        // A: 128 rows x 8 chunks(16B) = 1024 chunks
        #pragma unroll
        for (int i = 0; i < 4; i++) {
            int idx = tid + i * NTHREADS;
            int rr = idx >> 3, c = idx & 7;
            cp_async16(sa + (uint32_t)rr * ROW_BYTES + (uint32_t)c * 16,
                       gA + (size_t)rr * K_TOTAL + c * 8);
        }
        // B: 128 rows x 8 chunks = 1024 chunks
        #pragma unroll
        for (int i = 0; i < 4; i++) {
            int idx = tid + i * NTHREADS;
            int rr = idx >> 3, c = idx & 7;
            cp_async16(sb + (uint32_t)rr * ROW_BYTES + (uint32_t)c * 16,
                       gW + (size_t)rr * K_TOTAL + c * 8);
        }
    };

    // Accumulators: 4 (m16) x 4 (n8) tiles, 4 floats each = 64 regs
    float acc[4][4][4];
    #pragma unroll
    for (int mi = 0; mi < 4; mi++)
        #pragma unroll
        for (int nj = 0; nj < 4; nj++)
            #pragma unroll
            for (int c = 0; c < 4; c++)
                acc[mi][nj][c] = 0.0f;

    // Pipeline prologue
    #pragma unroll
    for (int s = 0; s < STAGES - 1; s++) {
        issue_copy(s, s);
        cp_commit();
    }

    // ldmatrix lane addressing: rows = base + (lane&15), k-halfword offset = (lane>>4)*16B
    const uint32_t lane_row  = (uint32_t)(lane & 15) * ROW_BYTES;
    const uint32_t lane_koff = (uint32_t)(lane >> 4) * 16;   // bytes

    for (int kt = 0; kt < KITERS; kt++) {
        cp_wait_group<STAGES - 2>();
        __syncthreads();   // single sync per iter: also orders next issue vs prev compute

        int knext = kt + STAGES - 1;
        if (knext < KITERS) issue_copy(knext, knext % STAGES);
        cp_commit();

        const int stage = kt % STAGES;
        const uint32_t sa = smem_u32 + SMEM_BIAS_BYTES + (uint32_t)stage * STAGE_BYTES;
        const uint32_t sb = sa + A_STAGE_BYTES;
        const uint32_t a_base = sa + (uint32_t)(wm * 64) * ROW_BYTES + lane_row + lane_koff;
        const uint32_t b_base = sb + (uint32_t)(wn * 32) * ROW_BYTES + lane_row + lane_koff;

        #pragma unroll
        for (int ks = 0; ks < BK / 16; ks++) {
            const uint32_t koff = (uint32_t)ks * 32;   // 16 halves = 32 bytes
            uint32_t a[4][4], b[2][4];
            #pragma unroll
            for (int mi = 0; mi < 4; mi++)
                ldsm_x4(a[mi][0], a[mi][1], a[mi][2], a[mi][3],
                        a_base + (uint32_t)(mi * 16) * ROW_BYTES + koff);
            #pragma unroll
            for (int nb = 0; nb < 2; nb++)
                ldsm_x4(b[nb][0], b[nb][1], b[nb][2], b[nb][3],
                        b_base + (uint32_t)(nb * 16) * ROW_BYTES + koff);
            // a frag order matches mma A; b: r0=n0-7 k0-7, r1=n8-15 k0-7, r2=n0-7 k8-15, r3=n8-15 k8-15
            #pragma unroll
            for (int mi = 0; mi < 4; mi++)
                #pragma unroll
                for (int nb = 0; nb < 2; nb++) {
                    mma_16816(acc[mi][nb*2][0], acc[mi][nb*2][1], acc[mi][nb*2][2], acc[mi][nb*2][3],
                              a[mi][0], a[mi][1], a[mi][2], a[mi][3], b[nb][0], b[nb][2]);
                    mma_16816(acc[mi][nb*2+1][0], acc[mi][nb*2+1][1], acc[mi][nb*2+1][2], acc[mi][nb*2+1][3],
                              a[mi][0], a[mi][1], a[mi][2], a[mi][3], b[nb][1], b[nb][3]);
                }
        }
    }
    __syncthreads();   // protect smem reuse for epilogue staging

    // ---- Epilogue: acc regs -> smem staging -> +bias -> coalesced gmem stores
    // m16n8 f32 frag layout: c0=[l/4][2*(l%4)], c1=+1 col, c2/c3 at row+8
    float* staging = reinterpret_cast<float*>(smem + SMEM_BIAS_BYTES);
    {
        const int r_in = lane >> 2;
        const int c_in = (lane & 3) * 2;
        #pragma unroll
        for (int mi = 0; mi < 4; mi++)
            #pragma unroll
            for (int nj = 0; nj < 4; nj++) {
                int rr = wm * 64 + mi * 16 + r_in;
                int cc = wn * 32 + nj * 8 + c_in;
                *reinterpret_cast<float2*>(staging + (size_t)rr * EPI_PITCH + cc)
                    = make_float2(acc[mi][nj][0], acc[mi][nj][1]);
                *reinterpret_cast<float2*>(staging + (size_t)(rr + 8) * EPI_PITCH + cc)
                    = make_float2(acc[mi][nj][2], acc[mi][nj][3]);
            }
    }
    __syncthreads();

    // Coalesced write-out: 128 rows x 32 float4
    #pragma unroll 4
    for (int idx = tid; idx < BM * (BN / 4); idx += NTHREADS) {
        int rr = idx >> 5;
        int c4 = idx & 31;
        float4 v = *reinterpret_cast<const float4*>(staging + (size_t)rr * EPI_PITCH + c4 * 4);
        v.x += sbias[c4 * 4 + 0];
        v.y += sbias[c4 * 4 + 1];
        v.z += sbias[c4 * 4 + 2];
        v.w += sbias[c4 * 4 + 3];
        *reinterpret_cast<float4*>(out + (size_t)(m0 + rr) * N_TOTAL + n0 + c4 * 4) = v;
    }
}

// ============================================================
// Host launcher
// ============================================================
extern "C" void kernel_launch(void* const* d_in, const int* in_sizes, int n_in,
                              void* d_out, int out_size) {
    const float* x    = (const float*)d_in[0];   // [16384, 4096]
    const float* w    = (const float*)d_in[1];   // [4096, 4096]
    const float* bias = (const float*)d_in[2];   // [4096]
    float* out = (float*)d_out;

    __half* xh = nullptr;
    __half* wh = nullptr;
    cudaGetSymbolAddress((void**)&xh, g_xh);
    cudaGetSymbolAddress((void**)&wh, g_wh);

    // fp32 -> fp16 conversion
    {
        int n4x = (int)(((size_t)M_TOTAL * K_TOTAL) / 4);
        int n4w = (int)(((size_t)N_TOTAL * K_TOTAL) / 4);
        f32_to_f16_kernel<<<(n4x + 255) / 256, 256>>>((const float4*)x, (uint2*)xh, n4x);
        f32_to_f16_kernel<<<(n4w + 255) / 256, 256>>>((const float4*)w, (uint2*)wh, n4w);
    }

    static bool attr_set = false;
    if (!attr_set) {
        cudaFuncSetAttribute(gemm_f16_kernel, cudaFuncAttributeMaxDynamicSharedMemorySize,
                             SMEM_TOTAL);
        attr_set = true;
    }
    gemm_f16_kernel<<<GRID_M * GRID_N, NTHREADS, SMEM_TOTAL>>>(xh, wh, bias, out);
}